// round 1
// baseline (speedup 1.0000x reference)
#include <cuda_runtime.h>
#include <math.h>

// Problem constants
#define Bn   16
#define Nn   16
#define Hh   896
#define Ww   896
#define Cc   3
#define PH   300
#define PW   300
#define MINPH 60.0f

#define NPIX (Hh*Ww)                         // 802816
#define IMG_ELEMS ((size_t)Bn*Hh*Ww*Cc)      // 38,535,168

// Output layout (flattened, concatenated in reference return order, float32):
//   imgs_out [B,H,W,C], pboxes [B,N,4], valid [B,N], transform_decisions [B,N,3], grads [PH,PW,C]
#define OFF_PBOX  (IMG_ELEMS)
#define OFF_VALID (OFF_PBOX + (size_t)Bn*Nn*4)
#define OFF_TD    (OFF_VALID + (size_t)Bn*Nn)
#define OFF_GRADS (OFF_TD + (size_t)Bn*Nn*3)

// Scratch (no allocations allowed -> __device__ globals)
__device__ int4   g_boxi[Bn*Nn];     // {yp, xp, ph, pw} ints; ph=pw=0 if invalid
__device__ float4 g_boxf[Bn*Nn];     // {inv_y, yp*inv_y+0.5, inv_x, xp*inv_x+0.5}
__device__ float  g_A[Bn*Nn*PH];     // row weight sums per box
__device__ float  g_Bw[Bn*Nn*PW];    // col weight sums per box

// ---------------------------------------------------------------------------
// Kernel 1: per-box setup (_create), small outputs (pboxes, valid, td copy)
// ---------------------------------------------------------------------------
__global__ void k_setup(const float* __restrict__ boxes,
                        const int*   __restrict__ td,
                        float* __restrict__ out)
{
    int t = threadIdx.x;           // t = b*N + n, 256 threads
    if (t >= Bn*Nn) return;

    float ymin = boxes[t*4+0];
    float xmin = boxes[t*4+1];
    float ymax = boxes[t*4+2];
    float xmax = boxes[t*4+3];

    float h  = ymax - ymin;
    float w  = xmax - xmin;
    float pw = h * 0.5f;           // SCALE = 0.5 (note: derived from h)
    float ph = 1.0f * pw;          // ASPECT = 1.0
    float oy = ymin + h * 0.5f;
    float ox = xmin + w * 0.5f;
    float yp = fmaxf(oy - ph * 0.5f, 0.0f);
    float xp = fmaxf(ox - pw * 0.5f, 0.0f);
    if (yp + ph > (float)Hh) yp = (float)Hh - ph;
    if (xp + pw > (float)Ww) xp = (float)Ww - pw;

    // pboxes output (float, pre-truncation values)
    float* out_pb = out + OFF_PBOX;
    out_pb[t*4+0] = yp; out_pb[t*4+1] = xp; out_pb[t*4+2] = ph; out_pb[t*4+3] = pw;

    bool valid = (ph > MINPH);
    out[OFF_VALID + t] = valid ? 1.0f : 0.0f;

    // transform_decisions passthrough (bool -> 0/1 float)
    #pragma unroll
    for (int k = 0; k < 3; ++k)
        out[OFF_TD + (size_t)t*3 + k] = (td[t*3+k] != 0) ? 1.0f : 0.0f;

    if (!valid) {
        g_boxi[t] = make_int4(0, 0, 0, 0);
        g_boxf[t] = make_float4(0.f, 0.f, 0.f, 0.f);
    } else {
        int ypi = (int)yp;                 // floats are >= 0 -> trunc == floor
        int xpi = (int)xp;
        int phi = max((int)ph, 1);
        int pwi = max((int)pw, 1);
        g_boxi[t] = make_int4(ypi, xpi, phi, pwi);
        // match jax: scale = ph_i/PH (f32 div), inv = 1/scale (f32 div)
        float s0 = (float)phi / (float)PH;  float inv0 = 1.0f / s0;
        float s1 = (float)pwi / (float)PW;  float inv1 = 1.0f / s1;
        g_boxf[t] = make_float4(inv0, (float)ypi * inv0 + 0.5f,
                                inv1, (float)xpi * inv1 + 0.5f);
    }
}

// ---------------------------------------------------------------------------
// Kernel 2: image composite. Per pixel: last valid covering box wins ->
// interior bilinear sample of patch; else passthrough of images.
// ---------------------------------------------------------------------------
__global__ void k_image(const float* __restrict__ images,
                        const float* __restrict__ patch,
                        float* __restrict__ out)
{
    const int b = blockIdx.y;
    __shared__ int4   sbi[Nn];
    __shared__ float4 sbf[Nn];
    if (threadIdx.x < Nn) {
        sbi[threadIdx.x] = g_boxi[b*Nn + threadIdx.x];
        sbf[threadIdx.x] = g_boxf[b*Nn + threadIdx.x];
    }
    __syncthreads();

    int pix = blockIdx.x * blockDim.x + threadIdx.x;
    if (pix >= NPIX) return;
    int i = pix / Ww;
    int j = pix - i * Ww;

    int hit = -1;
    for (int n = Nn - 1; n >= 0; --n) {
        int4 bx = sbi[n];
        if ((unsigned)(i - bx.x) < (unsigned)bx.z &&
            (unsigned)(j - bx.y) < (unsigned)bx.w) { hit = n; break; }
    }

    size_t base = ((size_t)b * NPIX + (size_t)pix) * 3;
    if (hit < 0) {
        out[base+0] = images[base+0];
        out[base+1] = images[base+1];
        out[base+2] = images[base+2];
    } else {
        float4 f = sbf[hit];
        float u = ((float)i + 0.5f) * f.x - f.y;   // in (0, PH-1): interior
        float v = ((float)j + 0.5f) * f.z - f.w;
        float fu = floorf(u), fv = floorf(v);
        float du = u - fu,    dv = v - fv;
        int r0 = (int)fu, c0 = (int)fv;
        const float* p00 = patch + ((size_t)r0 * PW + c0) * 3;
        float w00 = (1.0f-du)*(1.0f-dv);
        float w01 = (1.0f-du)*dv;
        float w10 = du*(1.0f-dv);
        float w11 = du*dv;
        #pragma unroll
        for (int c = 0; c < 3; ++c)
            out[base+c] = w00*p00[c] + w01*p00[3+c] + w10*p00[PW*3+c] + w11*p00[PW*3+3+c];
    }
}

// ---------------------------------------------------------------------------
// Kernel 3: per-box separable VJP vectors.
// A[p] = sum over window rows k of tri((k+0.5)*inv - 0.5 - p). Same for B.
// Each p receives contributions from <=2 window rows (scale < 1).
// ---------------------------------------------------------------------------
__global__ void k_ab()
{
    int bn = blockIdx.x;
    int p  = threadIdx.x;
    if (p >= PH) return;
    int4   bx = g_boxi[bn];
    float4 f  = g_boxf[bn];
    float a = 0.0f, bb = 0.0f;
    if (bx.z > 0) {
        // rows (A)
        {
            float r = (float)bx.z / (float)PH;   // scale < 1
            float inv = f.x;
            int k0 = (int)floorf(((float)p + 0.5f) * r - 0.5f) - 2;
            #pragma unroll
            for (int dk = 0; dk < 5; ++dk) {
                int k = k0 + dk;
                if (k < 0 || k >= bx.z) continue;
                float u = ((float)k + 0.5f) * inv - 0.5f;
                float wgt = 1.0f - fabsf(u - (float)p);
                if (wgt > 0.0f) a += wgt;
            }
        }
        // cols (B)
        {
            float r = (float)bx.w / (float)PW;
            float inv = f.z;
            int k0 = (int)floorf(((float)p + 0.5f) * r - 0.5f) - 2;
            #pragma unroll
            for (int dk = 0; dk < 5; ++dk) {
                int k = k0 + dk;
                if (k < 0 || k >= bx.w) continue;
                float u = ((float)k + 0.5f) * inv - 0.5f;
                float wgt = 1.0f - fabsf(u - (float)p);
                if (wgt > 0.0f) bb += wgt;
            }
        }
    }
    g_A [bn*PH + p] = a;
    g_Bw[bn*PW + p] = bb;
}

// ---------------------------------------------------------------------------
// Kernel 4: grads[p,q,c] = sum_b ( sum_n A_bn[p]*B_bn[q] ) * hist_grad[b,p,q,c]
// 16x16 (p,q) tile per block; A/B slices staged in smem (32 KB).
// ---------------------------------------------------------------------------
__global__ void k_grads(const float* __restrict__ hg, float* __restrict__ outg)
{
    __shared__ float As[Bn*Nn][16];
    __shared__ float Bs[Bn*Nn][16];
    int tx = threadIdx.x & 15;
    int ty = threadIdx.x >> 4;
    int p0 = blockIdx.y * 16;
    int q0 = blockIdx.x * 16;

    for (int idx = threadIdx.x; idx < Bn*Nn*16; idx += 256) {
        int bn = idx >> 4;
        int e  = idx & 15;
        As[bn][e] = (p0 + e < PH) ? g_A [bn*PH + p0 + e] : 0.0f;
        Bs[bn][e] = (q0 + e < PW) ? g_Bw[bn*PW + q0 + e] : 0.0f;
    }
    __syncthreads();

    int p = p0 + ty, q = q0 + tx;
    if (p >= PH || q >= PW) return;

    float a0 = 0.f, a1 = 0.f, a2 = 0.f;
    for (int b = 0; b < Bn; ++b) {
        float s = 0.f;
        #pragma unroll
        for (int n = 0; n < Nn; ++n)
            s += As[b*Nn + n][ty] * Bs[b*Nn + n][tx];
        size_t hb = (((size_t)b * PH + p) * PW + q) * 3;
        a0 += s * hg[hb+0];
        a1 += s * hg[hb+1];
        a2 += s * hg[hb+2];
    }
    size_t gb = ((size_t)p * PW + q) * 3;
    outg[gb+0] = a0;
    outg[gb+1] = a1;
    outg[gb+2] = a2;
}

// ---------------------------------------------------------------------------
extern "C" void kernel_launch(void* const* d_in, const int* in_sizes, int n_in,
                              void* d_out, int out_size)
{
    const float* boxes  = (const float*)d_in[0];
    const float* images = (const float*)d_in[1];
    const float* patch  = (const float*)d_in[2];
    const float* hg     = (const float*)d_in[3];
    const int*   td     = (const int*)  d_in[4];   // bool -> int32 assumption
    float* out = (float*)d_out;

    k_setup<<<1, 256>>>(boxes, td, out);
    k_image<<<dim3(NPIX/256, Bn), 256>>>(images, patch, out);
    k_ab<<<Bn*Nn, 320>>>();
    k_grads<<<dim3((PW+15)/16, (PH+15)/16), 256>>>(hg, out + OFF_GRADS);
}